// round 1
// baseline (speedup 1.0000x reference)
#include <cuda_runtime.h>

#define B_ 64
#define N_ 25
#define C_ 128
#define T_ 256

typedef unsigned long long ull;

// ---------------- device scratch (no runtime allocation allowed) ----------------
__device__ float g_xm[B_ * N_ * C_ * T_];      // node-mixed x: [b][m][c][t]  (~210MB)
__device__ float g_A[384 * 128];               // Weff flattened: row kk = k*128+c, col o
__device__ float g_sfull[C_], g_s0[C_], g_sT[C_];
__device__ float g_tcs[C_], g_tcb[C_], g_bns[C_], g_bnb[C_], g_bconv[C_];
__device__ float g_rowsum[N_];

// packed f32x2 FMA (sm_100+): d = a*b + d elementwise on packed pairs
#define FMA2(d, a, b) asm("fma.rn.f32x2 %0, %1, %2, %0;" : "+l"(d) : "l"(a), "l"(b))

__device__ __forceinline__ float2 u2f(ull u) {
    float2 f;
    f.x = __uint_as_float((unsigned)(u & 0xffffffffull));
    f.y = __uint_as_float((unsigned)(u >> 32));
    return f;
}

// ---------------- kernel 1: fold weights / biases / BN params ----------------
// blocks 0..383: g_A[kk][o] = sum_i Wc[o,i,k] * Wg[i,c]   (kk = k*128 + c)
// block 384: bias vectors, BN scale/shift, adj row sums
__global__ void precompute_kernel(
    const float* __restrict__ Wg, const float* __restrict__ bg,
    const float* __restrict__ Wc, const float* __restrict__ bc,
    const float* __restrict__ tg, const float* __restrict__ tb,
    const float* __restrict__ tm, const float* __restrict__ tv,
    const float* __restrict__ bng, const float* __restrict__ bnbt,
    const float* __restrict__ bnm, const float* __restrict__ bnv,
    const float* __restrict__ adj)
{
    int blk = blockIdx.x;
    int o = threadIdx.x;  // 128 threads
    if (blk < 384) {
        int k = blk >> 7, c = blk & 127;
        float s = 0.f;
        #pragma unroll 4
        for (int i = 0; i < C_; i++)
            s += Wc[(o * C_ + i) * 3 + k] * Wg[i * C_ + c];
        g_A[blk * C_ + o] = s;
    } else {
        float s0 = 0.f, s1 = 0.f, s2 = 0.f;
        for (int i = 0; i < C_; i++) {
            float b = bg[i];
            const float* w = &Wc[(o * C_ + i) * 3];
            s0 += w[0] * b; s1 += w[1] * b; s2 += w[2] * b;
        }
        g_sfull[o] = s0 + s1 + s2;
        g_s0[o] = s1 + s2;     // t==0: conv window misses k=0
        g_sT[o] = s0 + s1;     // t==T-1: misses k=2
        g_bconv[o] = bc[o];
        float ts = tg[o] * rsqrtf(tv[o] + 1e-5f);
        g_tcs[o] = ts; g_tcb[o] = tb[o] - tm[o] * ts;
        float bs = bng[o] * rsqrtf(bnv[o] + 1e-5f);
        g_bns[o] = bs; g_bnb[o] = bnbt[o] - bnm[o] * bs;
        if (o < N_) {
            float r = 0.f;
            for (int n = 0; n < N_; n++) r += adj[o * N_ + n];
            g_rowsum[o] = r;
        }
    }
}

// ---------------- kernel 2: node mix  xm[b,m,c,t] = sum_n adj[m,n] x[b,n,c,t] ----------------
__global__ __launch_bounds__(256) void mix_kernel(const float* __restrict__ x,
                                                  const float* __restrict__ adj)
{
    __shared__ float adjs[N_ * N_];
    int tid = threadIdx.x;
    for (int i = tid; i < N_ * N_; i += blockDim.x) adjs[i] = adj[i];
    __syncthreads();

    int b = blockIdx.y;
    int pos = blockIdx.x * blockDim.x + tid;  // float4 index in [0, C*T/4)
    const float4* xb = (const float4*)(x) + (size_t)b * N_ * (C_ * T_ / 4);
    float4* xmb = (float4*)(g_xm) + (size_t)b * N_ * (C_ * T_ / 4);

    float4 acc[N_];
    #pragma unroll
    for (int m = 0; m < N_; m++) acc[m] = make_float4(0.f, 0.f, 0.f, 0.f);

    #pragma unroll 1
    for (int n = 0; n < N_; n++) {
        float4 v = xb[n * (C_ * T_ / 4) + pos];
        #pragma unroll
        for (int m = 0; m < N_; m++) {
            float a = adjs[m * N_ + n];
            acc[m].x += a * v.x; acc[m].y += a * v.y;
            acc[m].z += a * v.z; acc[m].w += a * v.w;
        }
    }
    #pragma unroll
    for (int m = 0; m < N_; m++) xmb[m * (C_ * T_ / 4) + pos] = acc[m];
}

// ---------------- kernel 3: fused conv-GEMM + epilogue ----------------
// Per block: one (b, m) pair, o-tile = all 128, t-tile = 64.
// acc[o,t] = sum_{k,c} Weff[k][o][c] * xm_pad[c, t+k-1]  via 12 K-iters of BK=32.
// Uses fma.rn.f32x2 with A duplicated in smem so LDS.128 gives broadcast pairs.
#define BK 32
#define BN 64

__global__ __launch_bounds__(256) void stconv_kernel(const float* __restrict__ x,
                                                     float* __restrict__ out)
{
    __shared__ __align__(16) float As[BK][264];  // dup cols: 2*128 + 8 pad
    __shared__ __align__(16) float Bs[BK][BN];

    int tid = threadIdx.x;
    int tx = tid & 15;    // 16 groups over t (4 t each)
    int ty = tid >> 4;    // 16 groups over o (4+4 o each)
    int t0 = blockIdx.x * BN;
    int m = blockIdx.y;
    int b = blockIdx.z;

    const float* xm = g_xm + (size_t)(b * N_ + m) * C_ * T_;

    ull acc[8][2];
    #pragma unroll
    for (int i = 0; i < 8; i++) { acc[i][0] = 0ull; acc[i][1] = 0ull; }

    int ar = tid >> 3;   // A tile row 0..31
    int aq = tid & 7;
    int bt = tid & 63;   // B tile t 0..63
    int br = tid >> 6;   // B tile row base 0..3

    #pragma unroll 1
    for (int iter = 0; iter < 12; iter++) {
        int k = iter >> 2;
        int c0 = (iter & 3) * 32;
        int s = k - 1;

        // A tile: load Weff rows [k*128+c0+ar][0..127], store each value twice
        const float4* Ag = (const float4*)(g_A + (k * 128 + c0 + ar) * 128);
        #pragma unroll
        for (int e = 0; e < 4; e++) {
            int q = aq + 8 * e;          // float4 index 0..31 in source row
            float4 v = Ag[q];
            *(float4*)&As[ar][8 * q]     = make_float4(v.x, v.x, v.y, v.y);
            *(float4*)&As[ar][8 * q + 4] = make_float4(v.z, v.z, v.w, v.w);
        }
        // B tile: shifted xm columns with zero padding
        int tsrc = t0 + bt + s;
        bool inr = (tsrc >= 0) && (tsrc < T_);
        #pragma unroll
        for (int g = 0; g < 8; g++) {
            int ci = br + 4 * g;
            float v = inr ? xm[(c0 + ci) * T_ + tsrc] : 0.f;
            Bs[ci][bt] = v;
        }
        __syncthreads();

        #pragma unroll
        for (int kk = 0; kk < BK; kk++) {
            ulonglong2 a0 = *(const ulonglong2*)&As[kk][8 * ty];        // o = 4ty, 4ty+1
            ulonglong2 a1 = *(const ulonglong2*)&As[kk][8 * ty + 4];    // o = 4ty+2, 4ty+3
            ulonglong2 a2 = *(const ulonglong2*)&As[kk][128 + 8 * ty];  // o = 64+4ty, +1
            ulonglong2 a3 = *(const ulonglong2*)&As[kk][128 + 8 * ty + 4];
            ulonglong2 bv = *(const ulonglong2*)&Bs[kk][4 * tx];        // t pairs (0,1),(2,3)
            FMA2(acc[0][0], a0.x, bv.x); FMA2(acc[0][1], a0.x, bv.y);
            FMA2(acc[1][0], a0.y, bv.x); FMA2(acc[1][1], a0.y, bv.y);
            FMA2(acc[2][0], a1.x, bv.x); FMA2(acc[2][1], a1.x, bv.y);
            FMA2(acc[3][0], a1.y, bv.x); FMA2(acc[3][1], a1.y, bv.y);
            FMA2(acc[4][0], a2.x, bv.x); FMA2(acc[4][1], a2.x, bv.y);
            FMA2(acc[5][0], a2.y, bv.x); FMA2(acc[5][1], a2.y, bv.y);
            FMA2(acc[6][0], a3.x, bv.x); FMA2(acc[6][1], a3.x, bv.y);
            FMA2(acc[7][0], a3.y, bv.x); FMA2(acc[7][1], a3.y, bv.y);
        }
        __syncthreads();
    }

    // ---- epilogue: bias, tc-BN, relu, residual, blk-BN, relu ----
    float rs = g_rowsum[m];
    int base_t = t0 + 4 * tx;
    const float* xr = x + (size_t)(b * N_ + m) * C_ * T_;
    float* yo = out + (size_t)(b * N_ + m) * C_ * T_;

    #pragma unroll
    for (int i = 0; i < 8; i++) {
        int o = (i < 4) ? (4 * ty + i) : (64 + 4 * ty + i - 4);
        float tcs = g_tcs[o], tcb = g_tcb[o], bns = g_bns[o], bnb = g_bnb[o];
        float bcv = g_bconv[o];
        float bias_f = bcv + rs * g_sfull[o];
        float bias_0 = bcv + rs * g_s0[o];
        float bias_T = bcv + rs * g_sT[o];

        float4 r = *(const float4*)&xr[o * T_ + base_t];
        float2 p0 = u2f(acc[i][0]);
        float2 p1 = u2f(acc[i][1]);
        float v[4] = { p0.x, p0.y, p1.x, p1.y };
        float res[4] = { r.x, r.y, r.z, r.w };
        float ov[4];
        #pragma unroll
        for (int j = 0; j < 4; j++) {
            int t = base_t + j;
            float bias = bias_f;
            if (t == 0) bias = bias_0;
            else if (t == T_ - 1) bias = bias_T;
            float p = v[j] + bias;
            float y1 = fmaxf(tcs * p + tcb, 0.f);
            float y2 = y1 + res[j];
            ov[j] = fmaxf(bns * y2 + bnb, 0.f);
        }
        *(float4*)&yo[o * T_ + base_t] = make_float4(ov[0], ov[1], ov[2], ov[3]);
    }
}

// ---------------- launch ----------------
extern "C" void kernel_launch(void* const* d_in, const int* in_sizes, int n_in,
                              void* d_out, int out_size)
{
    const float* x   = (const float*)d_in[0];
    const float* adj = (const float*)d_in[1];
    const float* Wg  = (const float*)d_in[2];
    const float* bg  = (const float*)d_in[3];
    const float* Wc  = (const float*)d_in[4];
    const float* bc  = (const float*)d_in[5];
    const float* tg  = (const float*)d_in[6];
    const float* tb  = (const float*)d_in[7];
    const float* tm  = (const float*)d_in[8];
    const float* tv  = (const float*)d_in[9];
    const float* bng = (const float*)d_in[10];
    const float* bnb = (const float*)d_in[11];
    const float* bnm = (const float*)d_in[12];
    const float* bnv = (const float*)d_in[13];

    precompute_kernel<<<385, 128>>>(Wg, bg, Wc, bc, tg, tb, tm, tv, bng, bnb, bnm, bnv, adj);
    mix_kernel<<<dim3(C_ * T_ / 4 / 256, B_), 256>>>(x, adj);
    stconv_kernel<<<dim3(T_ / BN, N_, B_), 256>>>(x, (float*)d_out);
}

// round 2
// speedup vs baseline: 1.0002x; 1.0002x over previous
#include <cuda_runtime.h>

#define B_ 64
#define N_ 25
#define C_ 128
#define T_ 256

typedef unsigned long long ull;

// ---------------- device scratch (no runtime allocation allowed) ----------------
__device__ float g_xm[B_ * N_ * C_ * T_];      // node-mixed x: [b][m][c][t]  (~210MB)
__device__ float g_A[384 * 128];               // Weff flattened: row kk = k*128+c, col o
__device__ float g_sfull[C_], g_s0[C_], g_sT[C_];
__device__ float g_tcs[C_], g_tcb[C_], g_bns[C_], g_bnb[C_], g_bconv[C_];
__device__ float g_rowsum[N_];

// packed f32x2 FMA (sm_100+): d = a*b + d elementwise on packed pairs
#define FMA2(d, a, b) asm("fma.rn.f32x2 %0, %1, %2, %0;" : "+l"(d) : "l"(a), "l"(b))

__device__ __forceinline__ float2 u2f(ull u) {
    float2 f;
    f.x = __uint_as_float((unsigned)(u & 0xffffffffull));
    f.y = __uint_as_float((unsigned)(u >> 32));
    return f;
}

// ---------------- kernel 1: fold weights / biases / BN params ----------------
// blocks 0..383: g_A[kk][o] = sum_i Wc[o,i,k] * Wg[i,c]   (kk = k*128 + c)
// block 384: bias vectors, BN scale/shift, adj row sums
__global__ void precompute_kernel(
    const float* __restrict__ Wg, const float* __restrict__ bg,
    const float* __restrict__ Wc, const float* __restrict__ bc,
    const float* __restrict__ tg, const float* __restrict__ tb,
    const float* __restrict__ tm, const float* __restrict__ tv,
    const float* __restrict__ bng, const float* __restrict__ bnbt,
    const float* __restrict__ bnm, const float* __restrict__ bnv,
    const float* __restrict__ adj)
{
    int blk = blockIdx.x;
    int o = threadIdx.x;  // 128 threads
    if (blk < 384) {
        int k = blk >> 7, c = blk & 127;
        float s = 0.f;
        #pragma unroll 4
        for (int i = 0; i < C_; i++)
            s += Wc[(o * C_ + i) * 3 + k] * Wg[i * C_ + c];
        g_A[blk * C_ + o] = s;
    } else {
        float s0 = 0.f, s1 = 0.f, s2 = 0.f;
        for (int i = 0; i < C_; i++) {
            float b = bg[i];
            const float* w = &Wc[(o * C_ + i) * 3];
            s0 += w[0] * b; s1 += w[1] * b; s2 += w[2] * b;
        }
        g_sfull[o] = s0 + s1 + s2;
        g_s0[o] = s1 + s2;     // t==0: conv window misses k=0
        g_sT[o] = s0 + s1;     // t==T-1: misses k=2
        g_bconv[o] = bc[o];
        float ts = tg[o] * rsqrtf(tv[o] + 1e-5f);
        g_tcs[o] = ts; g_tcb[o] = tb[o] - tm[o] * ts;
        float bs = bng[o] * rsqrtf(bnv[o] + 1e-5f);
        g_bns[o] = bs; g_bnb[o] = bnbt[o] - bnm[o] * bs;
        if (o < N_) {
            float r = 0.f;
            for (int n = 0; n < N_; n++) r += adj[o * N_ + n];
            g_rowsum[o] = r;
        }
    }
}

// ---------------- kernel 2: node mix  xm[b,m,c,t] = sum_n adj[m,n] x[b,n,c,t] ----------------
__global__ __launch_bounds__(256) void mix_kernel(const float* __restrict__ x,
                                                  const float* __restrict__ adj)
{
    __shared__ float adjs[N_ * N_];
    int tid = threadIdx.x;
    for (int i = tid; i < N_ * N_; i += blockDim.x) adjs[i] = adj[i];
    __syncthreads();

    int b = blockIdx.y;
    int pos = blockIdx.x * blockDim.x + tid;  // float4 index in [0, C*T/4)
    const float4* xb = (const float4*)(x) + (size_t)b * N_ * (C_ * T_ / 4);
    float4* xmb = (float4*)(g_xm) + (size_t)b * N_ * (C_ * T_ / 4);

    float4 acc[N_];
    #pragma unroll
    for (int m = 0; m < N_; m++) acc[m] = make_float4(0.f, 0.f, 0.f, 0.f);

    #pragma unroll 1
    for (int n = 0; n < N_; n++) {
        float4 v = xb[n * (C_ * T_ / 4) + pos];
        #pragma unroll
        for (int m = 0; m < N_; m++) {
            float a = adjs[m * N_ + n];
            acc[m].x += a * v.x; acc[m].y += a * v.y;
            acc[m].z += a * v.z; acc[m].w += a * v.w;
        }
    }
    #pragma unroll
    for (int m = 0; m < N_; m++) xmb[m * (C_ * T_ / 4) + pos] = acc[m];
}

// ---------------- kernel 3: fused conv-GEMM + epilogue ----------------
// Per block: one (b, m) pair, o-tile = all 128, t-tile = 64.
// acc[o,t] = sum_{k,c} Weff[k][o][c] * xm_pad[c, t+k-1]  via 12 K-iters of BK=32.
// Uses fma.rn.f32x2 with A duplicated in smem so LDS.128 gives broadcast pairs.
#define BK 32
#define BN 64

__global__ __launch_bounds__(256) void stconv_kernel(const float* __restrict__ x,
                                                     float* __restrict__ out)
{
    __shared__ __align__(16) float As[BK][264];  // dup cols: 2*128 + 8 pad
    __shared__ __align__(16) float Bs[BK][BN];

    int tid = threadIdx.x;
    int tx = tid & 15;    // 16 groups over t (4 t each)
    int ty = tid >> 4;    // 16 groups over o (4+4 o each)
    int t0 = blockIdx.x * BN;
    int m = blockIdx.y;
    int b = blockIdx.z;

    const float* xm = g_xm + (size_t)(b * N_ + m) * C_ * T_;

    ull acc[8][2];
    #pragma unroll
    for (int i = 0; i < 8; i++) { acc[i][0] = 0ull; acc[i][1] = 0ull; }

    int ar = tid >> 3;   // A tile row 0..31
    int aq = tid & 7;
    int bt = tid & 63;   // B tile t 0..63
    int br = tid >> 6;   // B tile row base 0..3

    #pragma unroll 1
    for (int iter = 0; iter < 12; iter++) {
        int k = iter >> 2;
        int c0 = (iter & 3) * 32;
        int s = k - 1;

        // A tile: load Weff rows [k*128+c0+ar][0..127], store each value twice
        const float4* Ag = (const float4*)(g_A + (k * 128 + c0 + ar) * 128);
        #pragma unroll
        for (int e = 0; e < 4; e++) {
            int q = aq + 8 * e;          // float4 index 0..31 in source row
            float4 v = Ag[q];
            *(float4*)&As[ar][8 * q]     = make_float4(v.x, v.x, v.y, v.y);
            *(float4*)&As[ar][8 * q + 4] = make_float4(v.z, v.z, v.w, v.w);
        }
        // B tile: shifted xm columns with zero padding
        int tsrc = t0 + bt + s;
        bool inr = (tsrc >= 0) && (tsrc < T_);
        #pragma unroll
        for (int g = 0; g < 8; g++) {
            int ci = br + 4 * g;
            float v = inr ? xm[(c0 + ci) * T_ + tsrc] : 0.f;
            Bs[ci][bt] = v;
        }
        __syncthreads();

        #pragma unroll
        for (int kk = 0; kk < BK; kk++) {
            ulonglong2 a0 = *(const ulonglong2*)&As[kk][8 * ty];        // o = 4ty, 4ty+1
            ulonglong2 a1 = *(const ulonglong2*)&As[kk][8 * ty + 4];    // o = 4ty+2, 4ty+3
            ulonglong2 a2 = *(const ulonglong2*)&As[kk][128 + 8 * ty];  // o = 64+4ty, +1
            ulonglong2 a3 = *(const ulonglong2*)&As[kk][128 + 8 * ty + 4];
            ulonglong2 bv = *(const ulonglong2*)&Bs[kk][4 * tx];        // t pairs (0,1),(2,3)
            FMA2(acc[0][0], a0.x, bv.x); FMA2(acc[0][1], a0.x, bv.y);
            FMA2(acc[1][0], a0.y, bv.x); FMA2(acc[1][1], a0.y, bv.y);
            FMA2(acc[2][0], a1.x, bv.x); FMA2(acc[2][1], a1.x, bv.y);
            FMA2(acc[3][0], a1.y, bv.x); FMA2(acc[3][1], a1.y, bv.y);
            FMA2(acc[4][0], a2.x, bv.x); FMA2(acc[4][1], a2.x, bv.y);
            FMA2(acc[5][0], a2.y, bv.x); FMA2(acc[5][1], a2.y, bv.y);
            FMA2(acc[6][0], a3.x, bv.x); FMA2(acc[6][1], a3.x, bv.y);
            FMA2(acc[7][0], a3.y, bv.x); FMA2(acc[7][1], a3.y, bv.y);
        }
        __syncthreads();
    }

    // ---- epilogue: bias, tc-BN, relu, residual, blk-BN, relu ----
    float rs = g_rowsum[m];
    int base_t = t0 + 4 * tx;
    const float* xr = x + (size_t)(b * N_ + m) * C_ * T_;
    float* yo = out + (size_t)(b * N_ + m) * C_ * T_;

    #pragma unroll
    for (int i = 0; i < 8; i++) {
        int o = (i < 4) ? (4 * ty + i) : (64 + 4 * ty + i - 4);
        float tcs = g_tcs[o], tcb = g_tcb[o], bns = g_bns[o], bnb = g_bnb[o];
        float bcv = g_bconv[o];
        float bias_f = bcv + rs * g_sfull[o];
        float bias_0 = bcv + rs * g_s0[o];
        float bias_T = bcv + rs * g_sT[o];

        float4 r = *(const float4*)&xr[o * T_ + base_t];
        float2 p0 = u2f(acc[i][0]);
        float2 p1 = u2f(acc[i][1]);
        float v[4] = { p0.x, p0.y, p1.x, p1.y };
        float res[4] = { r.x, r.y, r.z, r.w };
        float ov[4];
        #pragma unroll
        for (int j = 0; j < 4; j++) {
            int t = base_t + j;
            float bias = bias_f;
            if (t == 0) bias = bias_0;
            else if (t == T_ - 1) bias = bias_T;
            float p = v[j] + bias;
            float y1 = fmaxf(tcs * p + tcb, 0.f);
            float y2 = y1 + res[j];
            ov[j] = fmaxf(bns * y2 + bnb, 0.f);
        }
        *(float4*)&yo[o * T_ + base_t] = make_float4(ov[0], ov[1], ov[2], ov[3]);
    }
}

// ---------------- launch ----------------
extern "C" void kernel_launch(void* const* d_in, const int* in_sizes, int n_in,
                              void* d_out, int out_size)
{
    const float* x   = (const float*)d_in[0];
    const float* adj = (const float*)d_in[1];
    const float* Wg  = (const float*)d_in[2];
    const float* bg  = (const float*)d_in[3];
    const float* Wc  = (const float*)d_in[4];
    const float* bc  = (const float*)d_in[5];
    const float* tg  = (const float*)d_in[6];
    const float* tb  = (const float*)d_in[7];
    const float* tm  = (const float*)d_in[8];
    const float* tv  = (const float*)d_in[9];
    const float* bng = (const float*)d_in[10];
    const float* bnb = (const float*)d_in[11];
    const float* bnm = (const float*)d_in[12];
    const float* bnv = (const float*)d_in[13];

    precompute_kernel<<<385, 128>>>(Wg, bg, Wc, bc, tg, tb, tm, tv, bng, bnb, bnm, bnv, adj);
    mix_kernel<<<dim3(C_ * T_ / 4 / 256, B_), 256>>>(x, adj);
    stconv_kernel<<<dim3(T_ / BN, N_, B_), 256>>>(x, (float*)d_out);
}

// round 4
// speedup vs baseline: 1.6551x; 1.6547x over previous
#include <cuda_runtime.h>
#include <cstdint>

#define B_ 64
#define N_ 25
#define C_ 128
#define T_ 256

// ---------------- device scratch ----------------
__device__ float g_z[B_ * N_ * C_ * T_];     // GEMM output per node (pre-mix), layout [b][n][o][t]
__device__ float g_A[384 * 128];             // Weff: row kk = k*128 + c, col o (tf32-rounded)
__device__ float g_WcT[3 * 128 * 128];       // Wc transposed: [k][i][o]
__device__ float g_sfull[C_], g_s0[C_], g_sT[C_];
__device__ float g_tcs[C_], g_tcb[C_], g_bns[C_], g_bnb[C_], g_bconv[C_];
__device__ float g_rowsum[N_];

__device__ __forceinline__ uint32_t f2tf32(float f) {
    uint32_t r;
    asm("cvt.rna.tf32.f32 %0, %1;" : "=r"(r) : "f"(f));
    return r;
}

__device__ __forceinline__ void mma_tf32(float* d, const uint32_t* a, const uint32_t* b) {
    asm volatile(
        "mma.sync.aligned.m16n8k8.row.col.f32.tf32.tf32.f32 "
        "{%0,%1,%2,%3}, {%4,%5,%6,%7}, {%8,%9}, {%0,%1,%2,%3};"
        : "+f"(d[0]), "+f"(d[1]), "+f"(d[2]), "+f"(d[3])
        : "r"(a[0]), "r"(a[1]), "r"(a[2]), "r"(a[3]), "r"(b[0]), "r"(b[1]));
}

// ---------------- precompute stage 1: transpose Wc [o][i][k] -> [k][i][o] ----------------
__global__ void transpose_wc_kernel(const float* __restrict__ Wc)
{
    int idx = blockIdx.x * 256 + threadIdx.x;   // 3*128*128 = 49152
    if (idx < 3 * 128 * 128) {
        int o = idx & 127, i = (idx >> 7) & 127, k = idx >> 14;
        g_WcT[idx] = Wc[(o * 128 + i) * 3 + k];  // write coalesced (o fastest)
    }
}

// ---------------- precompute stage 2: Weff[k][c][o] = sum_i Wc[o,i,k] * Wg[i,c] ----------------
__global__ void precompute_w_kernel(const float* __restrict__ Wg)
{
    int k = blockIdx.x >> 3;
    int c0 = (blockIdx.x & 7) * 16;
    int o = threadIdx.x;  // 128 threads
    __shared__ float wgs[128][17];
    #pragma unroll
    for (int e = 0; e < 16; e++) {
        int idx = o + 128 * e;          // 0..2047
        int i = idx >> 4, j = idx & 15;
        wgs[i][j] = Wg[i * 128 + c0 + j];
    }
    __syncthreads();
    float acc[16];
    #pragma unroll
    for (int j = 0; j < 16; j++) acc[j] = 0.f;
    const float* wt = g_WcT + k * 16384 + o;
    #pragma unroll 4
    for (int i = 0; i < 128; i++) {
        float w = wt[i * 128];
        #pragma unroll
        for (int j = 0; j < 16; j++) acc[j] += w * wgs[i][j];
    }
    #pragma unroll
    for (int j = 0; j < 16; j++)
        g_A[(k * 128 + c0 + j) * 128 + o] = __uint_as_float(f2tf32(acc[j]));
}

// ---------------- precompute stage 3: biases / BN folds / adj row sums ----------------
__global__ void precompute_bias_kernel(
    const float* __restrict__ bg, const float* __restrict__ Wc,
    const float* __restrict__ bc,
    const float* __restrict__ tg, const float* __restrict__ tb,
    const float* __restrict__ tm, const float* __restrict__ tv,
    const float* __restrict__ bng, const float* __restrict__ bnbt,
    const float* __restrict__ bnm, const float* __restrict__ bnv,
    const float* __restrict__ adj)
{
    int o = threadIdx.x;  // 128
    float s0 = 0.f, s1 = 0.f, s2 = 0.f;
    for (int i = 0; i < C_; i++) {
        float b = bg[i];
        const float* w = &Wc[(o * C_ + i) * 3];
        s0 += w[0] * b; s1 += w[1] * b; s2 += w[2] * b;
    }
    g_sfull[o] = s0 + s1 + s2;
    g_s0[o] = s1 + s2;     // t==0: window misses k=0
    g_sT[o] = s0 + s1;     // t==T-1: window misses k=2
    g_bconv[o] = bc[o];
    float ts = tg[o] * rsqrtf(tv[o] + 1e-5f);
    g_tcs[o] = ts; g_tcb[o] = tb[o] - tm[o] * ts;
    float bs = bng[o] * rsqrtf(bnv[o] + 1e-5f);
    g_bns[o] = bs; g_bnb[o] = bnbt[o] - bnm[o] * bs;
    if (o < N_) {
        float r = 0.f;
        for (int n = 0; n < N_; n++) r += adj[o * N_ + n];
        g_rowsum[o] = r;
    }
}

// ---------------- kernel 2: tf32 mma.sync conv-GEMM per (b, n, t-half) ----------------
// z[o, t] = sum_{k,c} Weff[k][c][o] * x[c, t+k-1]   (M=128 t, N=128 o, K=384)
// 8 warps: wm in {0,1} (64 t each), wn in {0..3} (32 o each).
#define XS_STRIDE 136
#define GEMM_SMEM (64 * 130 * 4)   // 33280 B: Ds[64][130]; xs[32][136] (17408 B) aliases front

__global__ __launch_bounds__(256) void stgemm_kernel(const float* __restrict__ x)
{
    extern __shared__ float smemf[];
    float* xs = smemf;              // [32][136]; col 3 = t0-1, 4..131 = t0..t0+127, 132 = t0+128
    float* Ds = smemf;              // [64][130] (epilogue reuse)

    int tid = threadIdx.x, lane = tid & 31, wid = tid >> 5;
    int wm = wid >> 2, wn = wid & 3;
    int t0 = blockIdx.x * 128;
    int node = blockIdx.z * N_ + blockIdx.y;
    const float* xp = x + (size_t)node * C_ * T_;

    float d[4][4][4];
    #pragma unroll
    for (int mt = 0; mt < 4; mt++)
        #pragma unroll
        for (int nt = 0; nt < 4; nt++)
            #pragma unroll
            for (int r = 0; r < 4; r++) d[mt][nt][r] = 0.f;

    const float* xsb = xs + (lane & 3) * XS_STRIDE + wm * 64 + (lane >> 2) + 3;
    const float* gAb = g_A + (lane & 3) * 128 + wn * 32 + (lane >> 2);

    #pragma unroll 1
    for (int cc = 0; cc < 4; cc++) {
        int c0 = cc * 32;
        __syncthreads();
        // stage x rows [c0..c0+32) x t window [t0-1, t0+128], tf32-rounded
        #pragma unroll
        for (int e = 0; e < 4; e++) {
            int idx = tid + 256 * e;               // 0..1023
            int ci = idx >> 5, tq = idx & 31;
            float4 v = *(const float4*)&xp[(c0 + ci) * T_ + t0 + 4 * tq];
            v.x = __uint_as_float(f2tf32(v.x));
            v.y = __uint_as_float(f2tf32(v.y));
            v.z = __uint_as_float(f2tf32(v.z));
            v.w = __uint_as_float(f2tf32(v.w));
            *(float4*)&xs[ci * XS_STRIDE + 4 + 4 * tq] = v;
        }
        if (tid < 32) {
            xs[tid * XS_STRIDE + 3] =
                (t0 > 0) ? __uint_as_float(f2tf32(xp[(c0 + tid) * T_ + t0 - 1])) : 0.f;
        } else if (tid < 64) {
            int ci = tid - 32;
            xs[ci * XS_STRIDE + 132] =
                (t0 + 128 < T_) ? __uint_as_float(f2tf32(xp[(c0 + ci) * T_ + t0 + 128])) : 0.f;
        }
        __syncthreads();

        #pragma unroll
        for (int k = 0; k < 3; k++) {
            int kk0 = k * 128 + c0;
            #pragma unroll
            for (int ks = 0; ks < 4; ks++) {
                int cl = 8 * ks;
                // B fragments straight from L2-resident g_A
                uint32_t b[4][2];
                const float* gp = gAb + (kk0 + cl) * 128;
                #pragma unroll
                for (int nt = 0; nt < 4; nt++) {
                    b[nt][0] = __float_as_uint(gp[8 * nt]);
                    b[nt][1] = __float_as_uint(gp[4 * 128 + 8 * nt]);
                }
                // A fragments from smem (conflict-free: banks (lane&3)*8 + lane>>2)
                const float* xq = xsb + cl * XS_STRIDE + k;
                #pragma unroll
                for (int mt = 0; mt < 4; mt++) {
                    uint32_t a[4];
                    a[0] = __float_as_uint(xq[mt * 16]);
                    a[1] = __float_as_uint(xq[mt * 16 + 8]);
                    a[2] = __float_as_uint(xq[4 * XS_STRIDE + mt * 16]);
                    a[3] = __float_as_uint(xq[4 * XS_STRIDE + mt * 16 + 8]);
                    #pragma unroll
                    for (int nt = 0; nt < 4; nt++) mma_tf32(d[mt][nt], a, b[nt]);
                }
            }
        }
    }

    // ---- epilogue: transpose through smem, coalesced store to g_z[o][t] ----
    float* zp = g_z + (size_t)node * C_ * T_;
    #pragma unroll 1
    for (int p = 0; p < 2; p++) {
        __syncthreads();
        if (wm == p) {
            #pragma unroll
            for (int mt = 0; mt < 4; mt++) {
                int r = mt * 16 + (lane >> 2);
                #pragma unroll
                for (int nt = 0; nt < 4; nt++) {
                    int cl = wn * 32 + nt * 8 + 2 * (lane & 3);
                    *(float2*)&Ds[r * 130 + cl]       = make_float2(d[mt][nt][0], d[mt][nt][1]);
                    *(float2*)&Ds[(r + 8) * 130 + cl] = make_float2(d[mt][nt][2], d[mt][nt][3]);
                }
            }
        }
        __syncthreads();
        #pragma unroll
        for (int i = 0; i < 32; i++) {
            int idx = tid + 256 * i;       // 0..8191
            int o = idx >> 6, tt = idx & 63;
            zp[o * T_ + t0 + p * 64 + tt] = Ds[tt * 130 + o];
        }
    }
}

// ---------------- kernel 3: fused node-mix + full epilogue ----------------
__global__ __launch_bounds__(256) void fuse_kernel(const float* __restrict__ x,
                                                   const float* __restrict__ adj,
                                                   float* __restrict__ out)
{
    __shared__ float adjs[N_ * N_];
    int tid = threadIdx.x;
    for (int i = tid; i < N_ * N_; i += 256) adjs[i] = adj[i];
    __syncthreads();

    int b = blockIdx.y;
    int pos = blockIdx.x * 256 + tid;       // float4 index in [0, C*T/4)
    int o = pos >> 6;
    int tbase = 4 * (pos & 63);

    const float4* zb = (const float4*)g_z + (size_t)b * N_ * (C_ * T_ / 4) + pos;
    const float4* xb = (const float4*)x + (size_t)b * N_ * (C_ * T_ / 4) + pos;
    float4* ob_ = (float4*)out + (size_t)b * N_ * (C_ * T_ / 4) + pos;

    float4 acc[N_];
    #pragma unroll
    for (int m = 0; m < N_; m++) acc[m] = make_float4(0.f, 0.f, 0.f, 0.f);

    #pragma unroll 1
    for (int n = 0; n < N_; n++) {
        float4 v = zb[n * (C_ * T_ / 4)];
        #pragma unroll
        for (int m = 0; m < N_; m++) {
            float a = adjs[m * N_ + n];
            acc[m].x += a * v.x; acc[m].y += a * v.y;
            acc[m].z += a * v.z; acc[m].w += a * v.w;
        }
    }

    float sfull = g_sfull[o], s0v = g_s0[o], sTv = g_sT[o], bcv = g_bconv[o];
    float tcs = g_tcs[o], tcb = g_tcb[o], bns = g_bns[o], bnb = g_bnb[o];
    bool e0 = (tbase == 0), eT = (tbase + 3 == T_ - 1);

    #pragma unroll 1
    for (int m = 0; m < N_; m++) {
        float rs = g_rowsum[m];
        float bias_f = bcv + rs * sfull;
        float v[4] = { acc[m].x, acc[m].y, acc[m].z, acc[m].w };
        float bias[4] = { bias_f, bias_f, bias_f, bias_f };
        if (e0) bias[0] = bcv + rs * s0v;
        if (eT) bias[3] = bcv + rs * sTv;
        float4 r = xb[m * (C_ * T_ / 4)];
        float res[4] = { r.x, r.y, r.z, r.w };
        float ov[4];
        #pragma unroll
        for (int j = 0; j < 4; j++) {
            float p = v[j] + bias[j];
            float y1 = fmaxf(tcs * p + tcb, 0.f);
            float y2 = y1 + res[j];
            ov[j] = fmaxf(bns * y2 + bnb, 0.f);
        }
        ob_[m * (C_ * T_ / 4)] = make_float4(ov[0], ov[1], ov[2], ov[3]);
    }
}

// ---------------- launch ----------------
extern "C" void kernel_launch(void* const* d_in, const int* in_sizes, int n_in,
                              void* d_out, int out_size)
{
    const float* x   = (const float*)d_in[0];
    const float* adj = (const float*)d_in[1];
    const float* Wg  = (const float*)d_in[2];
    const float* bg  = (const float*)d_in[3];
    const float* Wc  = (const float*)d_in[4];
    const float* bc  = (const float*)d_in[5];
    const float* tg  = (const float*)d_in[6];
    const float* tb  = (const float*)d_in[7];
    const float* tm  = (const float*)d_in[8];
    const float* tv  = (const float*)d_in[9];
    const float* bng = (const float*)d_in[10];
    const float* bnb = (const float*)d_in[11];
    const float* bnm = (const float*)d_in[12];
    const float* bnv = (const float*)d_in[13];

    transpose_wc_kernel<<<192, 256>>>(Wc);
    precompute_w_kernel<<<24, 128>>>(Wg);
    precompute_bias_kernel<<<1, 128>>>(bg, Wc, bc, tg, tb, tm, tv, bng, bnb, bnm, bnv, adj);
    stgemm_kernel<<<dim3(2, N_, B_), 256, GEMM_SMEM>>>(x);
    fuse_kernel<<<dim3(C_ * T_ / 4 / 256, B_), 256>>>(x, adj, (float*)d_out);
}